// round 2
// baseline (speedup 1.0000x reference)
#include <cuda_runtime.h>
#include <math.h>

#define BB 16
#define CC 512
#define TT 4096
#define FK 12
#define ACT_TILE 256

// ---------------- device scratch (no allocations allowed) ----------------
__device__ float g_filt[FK];
__device__ float g_w[CC * CC * 3];                 // normalized weights for the conv about to run
__device__ float g_buf1[(size_t)BB * CC * TT];     // activation output
__device__ float g_buf2[(size_t)BB * CC * TT];     // conv1 output
__device__ float g_x[(size_t)BB * CC * TT];        // running x between iterations

// ---------------- filter init (double precision, matches numpy) ----------------
__device__ double bessel_i0(double x) {
    double sum = 1.0, term = 1.0;
    for (int k = 1; k < 64; k++) {
        double t = x / (2.0 * k);
        term *= t * t;
        sum += term;
        if (term < 1e-18 * sum) break;
    }
    return sum;
}

__global__ void init_filter_kernel() {
    if (threadIdx.x == 0 && blockIdx.x == 0) {
        const double cutoff = 0.25;        // 0.5 / RATIO
        const double half_width = 0.3;     // 0.6 / RATIO
        const int half_size = FK / 2;      // 6
        double delta_f = 4.0 * half_width;
        double A = 2.285 * (half_size - 1) * M_PI * delta_f + 7.95;
        double beta;
        if (A > 50.0)       beta = 0.1102 * (A - 8.7);
        else if (A >= 21.0) beta = 0.5842 * pow(A - 21.0, 0.4) + 0.07886 * (A - 21.0);
        else                beta = 0.0;
        double i0b = bessel_i0(beta);
        double f[FK];
        double s = 0.0;
        for (int n = 0; n < FK; n++) {
            double r = 2.0 * n / (FK - 1.0) - 1.0;
            double w = bessel_i0(beta * sqrt(fmax(0.0, 1.0 - r * r))) / i0b;
            double tm = n - 5.5;                      // arange(-6,6)+0.5
            double xx = 2.0 * cutoff * tm;
            double snc = (fabs(xx) < 1e-12) ? 1.0 : sin(M_PI * xx) / (M_PI * xx);
            f[n] = 2.0 * cutoff * w * snc;
            s += f[n];
        }
        for (int n = 0; n < FK; n++) g_filt[n] = (float)(f[n] / s);
    }
}

// ---------------- fused aliasing activation: up2x -> snake -> down2x, * mask ----------------
// Derived polyphase form (filter is symmetric, so transposed-conv flip is identity):
//   x_p[i] = x[clamp(i-5, 0, T-1)]
//   u[2q]   = 2 * sum_j f[2j]   * x_p[q+2+j]
//   u[2q+1] = 2 * sum_j f[2j+1] * x_p[q+3+j]
//   s[m] = u[m] + invb * sin(u[m]*a)^2
//   z[t] = sum_k f[k] * s[clamp(2t+k-5, 0, 2T-1)]
__global__ __launch_bounds__(256) void act_kernel(
    const float* __restrict__ x, const float* __restrict__ mask,
    const float* __restrict__ alpha, const float* __restrict__ beta,
    float* __restrict__ out)
{
    __shared__ float sf[FK];
    __shared__ float sx[ACT_TILE + 12];
    __shared__ float ss[2 * ACT_TILE + 12];

    const int t0 = blockIdx.x * ACT_TILE;
    const int c  = blockIdx.y;
    const int b  = blockIdx.z;
    const int tid = threadIdx.x;
    const float* xr = x + ((size_t)(b * CC + c)) * TT;

    if (tid < FK) sf[tid] = g_filt[tid];
    // x_p indices t0-1 .. t0+ACT_TILE+10  -> shared slot i holds x_p[t0-1+i] = x[clamp(t0-6+i,...)]
    for (int i = tid; i < ACT_TILE + 12; i += 256) {
        int g = t0 - 6 + i;
        g = min(max(g, 0), TT - 1);
        sx[i] = xr[g];
    }
    __syncthreads();

    const float a    = expf(alpha[c]);
    const float invb = 1.0f / (expf(beta[c]) + 1e-5f);

    // ss slot si holds s[m] with m = 2*t0 - 6 + si
    for (int si = tid; si < 2 * ACT_TILE + 12; si += 256) {
        const int odd = si & 1;
        const int base = (si + odd) >> 1;   // even: si/2, odd: (si+1)/2
        float u = 0.f;
        #pragma unroll
        for (int j = 0; j < 6; j++) u = fmaf(sf[2 * j + odd], sx[base + j], u);
        u *= 2.0f;
        float sn = __sinf(u * a);
        ss[si] = fmaf(invb, sn * sn, u);
    }
    __syncthreads();

    const int t = t0 + tid;
    float z = 0.f;
    #pragma unroll
    for (int k = 0; k < FK; k++) {
        int m = 2 * t + k - 5;
        m = min(max(m, 0), 2 * TT - 1);
        z = fmaf(sf[k], ss[m - (2 * t0 - 6)], z);
    }
    out[((size_t)(b * CC + c)) * TT + t] = z * mask[(size_t)b * TT + t];
}

// ---------------- weight norm: w[o,c,k] = g[o] * v[o,c,k] / ||v[o]|| ----------------
__global__ __launch_bounds__(256) void wnorm_kernel(
    const float* __restrict__ v, const float* __restrict__ g, float* __restrict__ w)
{
    const int o = blockIdx.x;
    const float* vo = v + (size_t)o * (CC * 3);
    __shared__ float red[256];
    float s = 0.f;
    for (int i = threadIdx.x; i < CC * 3; i += 256) { float t = vo[i]; s = fmaf(t, t, s); }
    red[threadIdx.x] = s;
    __syncthreads();
    for (int st = 128; st > 0; st >>= 1) {
        if (threadIdx.x < st) red[threadIdx.x] += red[threadIdx.x + st];
        __syncthreads();
    }
    const float scale = g[o] / sqrtf(red[0]);
    for (int i = threadIdx.x; i < CC * 3; i += 256)
        w[(size_t)o * (CC * 3) + i] = vo[i] * scale;
}

// ---------------- dilated depthover-channel conv: y[b,o,t] = bias + sum_{c,k} w[o,c,k] x[b,c,t+(k-1)D]
// 128(o) x 128(t) block tile, 8x8 per thread, c-chunks of 8, 3 taps fused.
template<int D, bool HAS_RES, bool FUSE_MASK>
__global__ __launch_bounds__(256) void conv_kernel(
    const float* __restrict__ x, const float* __restrict__ w,
    const float* __restrict__ bias, const float* __restrict__ res,
    const float* __restrict__ mask, float* __restrict__ out)
{
    constexpr int RS = 128 + 2 * D;  // B tile row width (with halo)
    __shared__ float As[8 * 3 * 128];   // [(c_local*3 + tap)][o_local]
    __shared__ float Bs[8 * RS];        // [c_local][u], u=0 -> t0 - D

    const int t0 = blockIdx.x * 128;
    const int o0 = blockIdx.y * 128;
    const int b  = blockIdx.z;
    const int tid = threadIdx.x;
    const int tx = tid & 15;    // t groups (strided by 16)
    const int ty = tid >> 4;    // o groups (8 consecutive o)
    const float* xb = x + (size_t)b * CC * TT;

    float acc[8][8];
    #pragma unroll
    for (int i = 0; i < 8; i++)
        #pragma unroll
        for (int j = 0; j < 8; j++) acc[i][j] = 0.f;

    #pragma unroll 1
    for (int c0 = 0; c0 < CC; c0 += 8) {
        // ---- load W tile: 128 o x 8 c x 3 taps = 3072 floats = 768 float4
        #pragma unroll
        for (int r = 0; r < 3; r++) {
            int idx4 = tid + 256 * r;
            int o_l  = idx4 / 6;
            int part = idx4 - o_l * 6;
            const float4 v4 = *reinterpret_cast<const float4*>(
                w + (size_t)(o0 + o_l) * (CC * 3) + c0 * 3 + part * 4);
            As[(part * 4 + 0) * 128 + o_l] = v4.x;
            As[(part * 4 + 1) * 128 + o_l] = v4.y;
            As[(part * 4 + 2) * 128 + o_l] = v4.z;
            As[(part * 4 + 3) * 128 + o_l] = v4.w;
        }
        // ---- load X tile with halo, zero-padded outside [0,T)
        for (int i = tid; i < 8 * RS; i += 256) {
            int cl = i / RS;
            int u  = i - cl * RS;
            int t  = t0 - D + u;
            Bs[i] = (t >= 0 && t < TT) ? xb[(size_t)(c0 + cl) * TT + t] : 0.f;
        }
        __syncthreads();

        #pragma unroll 2
        for (int cl = 0; cl < 8; cl++) {
            float aa[3][8], bb[3][8];
            #pragma unroll
            for (int k = 0; k < 3; k++) {
                const float4* ap = reinterpret_cast<const float4*>(&As[(cl * 3 + k) * 128 + ty * 8]);
                float4 a0 = ap[0], a1 = ap[1];
                aa[k][0] = a0.x; aa[k][1] = a0.y; aa[k][2] = a0.z; aa[k][3] = a0.w;
                aa[k][4] = a1.x; aa[k][5] = a1.y; aa[k][6] = a1.z; aa[k][7] = a1.w;
                #pragma unroll
                for (int j = 0; j < 8; j++)
                    bb[k][j] = Bs[cl * RS + tx + 16 * j + k * D];
            }
            #pragma unroll
            for (int k = 0; k < 3; k++)
                #pragma unroll
                for (int i = 0; i < 8; i++)
                    #pragma unroll
                    for (int j = 0; j < 8; j++)
                        acc[i][j] = fmaf(aa[k][i], bb[k][j], acc[i][j]);
        }
        __syncthreads();
    }

    // ---- epilogue: + bias (+ residual) (* mask)
    #pragma unroll
    for (int i = 0; i < 8; i++) {
        const int o = o0 + ty * 8 + i;
        const float bo = bias[o];
        #pragma unroll
        for (int j = 0; j < 8; j++) {
            const int t = t0 + tx + 16 * j;
            const size_t idx = ((size_t)(b * CC + o)) * TT + t;
            float v = acc[i][j] + bo;
            if (HAS_RES)   v += res[idx];
            if (FUSE_MASK) v *= mask[(size_t)b * TT + t];
            out[idx] = v;
        }
    }
}

// ---------------- host ----------------
extern "C" void kernel_launch(void* const* d_in, const int* in_sizes, int n_in,
                              void* d_out, int out_size)
{
    const float* x    = (const float*)d_in[0];
    const float* mask = (const float*)d_in[1];
    const float* ina  = (const float*)d_in[2];
    const float* inb  = (const float*)d_in[3];
    const float* outa = (const float*)d_in[4];
    const float* outb = (const float*)d_in[5];
    const float* icv  = (const float*)d_in[6];
    const float* icg  = (const float*)d_in[7];
    const float* icb  = (const float*)d_in[8];
    const float* ocv  = (const float*)d_in[9];
    const float* ocg  = (const float*)d_in[10];
    const float* ocb  = (const float*)d_in[11];
    float* out = (float*)d_out;

    float *buf1, *buf2, *xbuf, *wbuf;
    cudaGetSymbolAddress((void**)&buf1, g_buf1);
    cudaGetSymbolAddress((void**)&buf2, g_buf2);
    cudaGetSymbolAddress((void**)&xbuf, g_x);
    cudaGetSymbolAddress((void**)&wbuf, g_w);

    init_filter_kernel<<<1, 32>>>();

    dim3 actGrid(TT / ACT_TILE, CC, BB);
    dim3 convGrid(TT / 128, CC / 128, BB);

    const float* cur = x;   // iteration input / residual
    for (int i = 0; i < 3; i++) {
        // x1 = act(cur) * mask
        act_kernel<<<actGrid, 256>>>(cur, mask, ina + i * CC, inb + i * CC, buf1);
        // conv1 (dilated)
        wnorm_kernel<<<CC, 256>>>(icv + (size_t)i * CC * CC * 3, icg + i * CC, wbuf);
        if (i == 0)
            conv_kernel<1, false, false><<<convGrid, 256>>>(buf1, wbuf, icb + i * CC, nullptr, nullptr, buf2);
        else if (i == 1)
            conv_kernel<3, false, false><<<convGrid, 256>>>(buf1, wbuf, icb + i * CC, nullptr, nullptr, buf2);
        else
            conv_kernel<5, false, false><<<convGrid, 256>>>(buf1, wbuf, icb + i * CC, nullptr, nullptr, buf2);
        // x2 = act(conv1) * mask
        act_kernel<<<actGrid, 256>>>(buf2, mask, outa + i * CC, outb + i * CC, buf1);
        // conv2 (dilation 1) + residual  (+ final mask on last iteration)
        wnorm_kernel<<<CC, 256>>>(ocv + (size_t)i * CC * CC * 3, ocg + i * CC, wbuf);
        if (i == 2)
            conv_kernel<1, true, true><<<convGrid, 256>>>(buf1, wbuf, ocb + i * CC, cur, mask, out);
        else
            conv_kernel<1, true, false><<<convGrid, 256>>>(buf1, wbuf, ocb + i * CC, cur, nullptr, xbuf);
        cur = xbuf;
    }
    (void)in_sizes; (void)n_in; (void)out_size;
}

// round 3
// speedup vs baseline: 1.0012x; 1.0012x over previous
#include <cuda_runtime.h>
#include <math.h>

#define BB 16
#define CC 512
#define TT 4096
#define FK 12
#define ACT_TILE 256

// ---------------- device scratch (no allocations allowed) ----------------
__device__ float g_filt[FK];
__device__ float g_w[CC * CC * 3];                 // normalized weights for the conv about to run
__device__ float g_buf1[(size_t)BB * CC * TT];     // activation output
__device__ float g_buf2[(size_t)BB * CC * TT];     // conv1 output
__device__ float g_x[(size_t)BB * CC * TT];        // running x between iterations

// ---------------- filter init (double precision, matches numpy) ----------------
__device__ double bessel_i0(double x) {
    double sum = 1.0, term = 1.0;
    for (int k = 1; k < 64; k++) {
        double t = x / (2.0 * k);
        term *= t * t;
        sum += term;
        if (term < 1e-18 * sum) break;
    }
    return sum;
}

__global__ void init_filter_kernel() {
    if (threadIdx.x == 0 && blockIdx.x == 0) {
        const double cutoff = 0.25;        // 0.5 / RATIO
        const double half_width = 0.3;     // 0.6 / RATIO
        const int half_size = FK / 2;      // 6
        double delta_f = 4.0 * half_width;
        double A = 2.285 * (half_size - 1) * M_PI * delta_f + 7.95;
        double beta;
        if (A > 50.0)       beta = 0.1102 * (A - 8.7);
        else if (A >= 21.0) beta = 0.5842 * pow(A - 21.0, 0.4) + 0.07886 * (A - 21.0);
        else                beta = 0.0;
        double i0b = bessel_i0(beta);
        double f[FK];
        double s = 0.0;
        for (int n = 0; n < FK; n++) {
            double r = 2.0 * n / (FK - 1.0) - 1.0;
            double w = bessel_i0(beta * sqrt(fmax(0.0, 1.0 - r * r))) / i0b;
            double tm = n - 5.5;                      // arange(-6,6)+0.5
            double xx = 2.0 * cutoff * tm;
            double snc = (fabs(xx) < 1e-12) ? 1.0 : sin(M_PI * xx) / (M_PI * xx);
            f[n] = 2.0 * cutoff * w * snc;
            s += f[n];
        }
        for (int n = 0; n < FK; n++) g_filt[n] = (float)(f[n] / s);
    }
}

// ---------------- fused aliasing activation: up2x -> snake -> down2x, * mask ----------------
// Derived polyphase form (filter is symmetric, so transposed-conv flip is identity):
//   x_p[i] = x[clamp(i-5, 0, T-1)]
//   u[2q]   = 2 * sum_j f[2j]   * x_p[q+2+j]
//   u[2q+1] = 2 * sum_j f[2j+1] * x_p[q+3+j]
//   s[m] = u[m] + invb * sin(u[m]*a)^2
//   z[t] = sum_k f[k] * s[clamp(2t+k-5, 0, 2T-1)]
__global__ __launch_bounds__(256) void act_kernel(
    const float* __restrict__ x, const float* __restrict__ mask,
    const float* __restrict__ alpha, const float* __restrict__ beta,
    float* __restrict__ out)
{
    __shared__ float sf[FK];
    __shared__ float sx[ACT_TILE + 12];
    __shared__ float ss[2 * ACT_TILE + 12];

    const int t0 = blockIdx.x * ACT_TILE;
    const int c  = blockIdx.y;
    const int b  = blockIdx.z;
    const int tid = threadIdx.x;
    const float* xr = x + ((size_t)(b * CC + c)) * TT;

    if (tid < FK) sf[tid] = g_filt[tid];
    // x_p indices t0-1 .. t0+ACT_TILE+10  -> shared slot i holds x_p[t0-1+i] = x[clamp(t0-6+i,...)]
    for (int i = tid; i < ACT_TILE + 12; i += 256) {
        int g = t0 - 6 + i;
        g = min(max(g, 0), TT - 1);
        sx[i] = xr[g];
    }
    __syncthreads();

    const float a    = expf(alpha[c]);
    const float invb = 1.0f / (expf(beta[c]) + 1e-5f);

    // ss slot si holds s[m] with m = 2*t0 - 6 + si
    for (int si = tid; si < 2 * ACT_TILE + 12; si += 256) {
        const int odd = si & 1;
        const int base = (si + odd) >> 1;   // even: si/2, odd: (si+1)/2
        float u = 0.f;
        #pragma unroll
        for (int j = 0; j < 6; j++) u = fmaf(sf[2 * j + odd], sx[base + j], u);
        u *= 2.0f;
        float sn = __sinf(u * a);
        ss[si] = fmaf(invb, sn * sn, u);
    }
    __syncthreads();

    const int t = t0 + tid;
    float z = 0.f;
    #pragma unroll
    for (int k = 0; k < FK; k++) {
        int m = 2 * t + k - 5;
        m = min(max(m, 0), 2 * TT - 1);
        z = fmaf(sf[k], ss[m - (2 * t0 - 6)], z);
    }
    out[((size_t)(b * CC + c)) * TT + t] = z * mask[(size_t)b * TT + t];
}

// ---------------- weight norm: w[o,c,k] = g[o] * v[o,c,k] / ||v[o]|| ----------------
__global__ __launch_bounds__(256) void wnorm_kernel(
    const float* __restrict__ v, const float* __restrict__ g, float* __restrict__ w)
{
    const int o = blockIdx.x;
    const float* vo = v + (size_t)o * (CC * 3);
    __shared__ float red[256];
    float s = 0.f;
    for (int i = threadIdx.x; i < CC * 3; i += 256) { float t = vo[i]; s = fmaf(t, t, s); }
    red[threadIdx.x] = s;
    __syncthreads();
    for (int st = 128; st > 0; st >>= 1) {
        if (threadIdx.x < st) red[threadIdx.x] += red[threadIdx.x + st];
        __syncthreads();
    }
    const float scale = g[o] / sqrtf(red[0]);
    for (int i = threadIdx.x; i < CC * 3; i += 256)
        w[(size_t)o * (CC * 3) + i] = vo[i] * scale;
}

// ---------------- dilated depthover-channel conv: y[b,o,t] = bias + sum_{c,k} w[o,c,k] x[b,c,t+(k-1)D]
// 128(o) x 128(t) block tile, 8x8 per thread, c-chunks of 8, 3 taps fused.
template<int D, bool HAS_RES, bool FUSE_MASK>
__global__ __launch_bounds__(256) void conv_kernel(
    const float* __restrict__ x, const float* __restrict__ w,
    const float* __restrict__ bias, const float* __restrict__ res,
    const float* __restrict__ mask, float* __restrict__ out)
{
    constexpr int RS = 128 + 2 * D;  // B tile row width (with halo)
    __shared__ float As[8 * 3 * 128];   // [(c_local*3 + tap)][o_local]
    __shared__ float Bs[8 * RS];        // [c_local][u], u=0 -> t0 - D

    const int t0 = blockIdx.x * 128;
    const int o0 = blockIdx.y * 128;
    const int b  = blockIdx.z;
    const int tid = threadIdx.x;
    const int tx = tid & 15;    // t groups (strided by 16)
    const int ty = tid >> 4;    // o groups (8 consecutive o)
    const float* xb = x + (size_t)b * CC * TT;

    float acc[8][8];
    #pragma unroll
    for (int i = 0; i < 8; i++)
        #pragma unroll
        for (int j = 0; j < 8; j++) acc[i][j] = 0.f;

    #pragma unroll 1
    for (int c0 = 0; c0 < CC; c0 += 8) {
        // ---- load W tile: 128 o x 8 c x 3 taps = 3072 floats = 768 float4
        #pragma unroll
        for (int r = 0; r < 3; r++) {
            int idx4 = tid + 256 * r;
            int o_l  = idx4 / 6;
            int part = idx4 - o_l * 6;
            const float4 v4 = *reinterpret_cast<const float4*>(
                w + (size_t)(o0 + o_l) * (CC * 3) + c0 * 3 + part * 4);
            As[(part * 4 + 0) * 128 + o_l] = v4.x;
            As[(part * 4 + 1) * 128 + o_l] = v4.y;
            As[(part * 4 + 2) * 128 + o_l] = v4.z;
            As[(part * 4 + 3) * 128 + o_l] = v4.w;
        }
        // ---- load X tile with halo, zero-padded outside [0,T)
        for (int i = tid; i < 8 * RS; i += 256) {
            int cl = i / RS;
            int u  = i - cl * RS;
            int t  = t0 - D + u;
            Bs[i] = (t >= 0 && t < TT) ? xb[(size_t)(c0 + cl) * TT + t] : 0.f;
        }
        __syncthreads();

        #pragma unroll 2
        for (int cl = 0; cl < 8; cl++) {
            float aa[3][8], bb[3][8];
            #pragma unroll
            for (int k = 0; k < 3; k++) {
                const float4* ap = reinterpret_cast<const float4*>(&As[(cl * 3 + k) * 128 + ty * 8]);
                float4 a0 = ap[0], a1 = ap[1];
                aa[k][0] = a0.x; aa[k][1] = a0.y; aa[k][2] = a0.z; aa[k][3] = a0.w;
                aa[k][4] = a1.x; aa[k][5] = a1.y; aa[k][6] = a1.z; aa[k][7] = a1.w;
                #pragma unroll
                for (int j = 0; j < 8; j++)
                    bb[k][j] = Bs[cl * RS + tx + 16 * j + k * D];
            }
            #pragma unroll
            for (int k = 0; k < 3; k++)
                #pragma unroll
                for (int i = 0; i < 8; i++)
                    #pragma unroll
                    for (int j = 0; j < 8; j++)
                        acc[i][j] = fmaf(aa[k][i], bb[k][j], acc[i][j]);
        }
        __syncthreads();
    }

    // ---- epilogue: + bias (+ residual) (* mask)
    #pragma unroll
    for (int i = 0; i < 8; i++) {
        const int o = o0 + ty * 8 + i;
        const float bo = bias[o];
        #pragma unroll
        for (int j = 0; j < 8; j++) {
            const int t = t0 + tx + 16 * j;
            const size_t idx = ((size_t)(b * CC + o)) * TT + t;
            float v = acc[i][j] + bo;
            if (HAS_RES)   v += res[idx];
            if (FUSE_MASK) v *= mask[(size_t)b * TT + t];
            out[idx] = v;
        }
    }
}

// ---------------- host ----------------
extern "C" void kernel_launch(void* const* d_in, const int* in_sizes, int n_in,
                              void* d_out, int out_size)
{
    const float* x    = (const float*)d_in[0];
    const float* mask = (const float*)d_in[1];
    const float* ina  = (const float*)d_in[2];
    const float* inb  = (const float*)d_in[3];
    const float* outa = (const float*)d_in[4];
    const float* outb = (const float*)d_in[5];
    const float* icv  = (const float*)d_in[6];
    const float* icg  = (const float*)d_in[7];
    const float* icb  = (const float*)d_in[8];
    const float* ocv  = (const float*)d_in[9];
    const float* ocg  = (const float*)d_in[10];
    const float* ocb  = (const float*)d_in[11];
    float* out = (float*)d_out;

    float *buf1, *buf2, *xbuf, *wbuf;
    cudaGetSymbolAddress((void**)&buf1, g_buf1);
    cudaGetSymbolAddress((void**)&buf2, g_buf2);
    cudaGetSymbolAddress((void**)&xbuf, g_x);
    cudaGetSymbolAddress((void**)&wbuf, g_w);

    init_filter_kernel<<<1, 32>>>();

    dim3 actGrid(TT / ACT_TILE, CC, BB);
    dim3 convGrid(TT / 128, CC / 128, BB);

    const float* cur = x;   // iteration input / residual
    for (int i = 0; i < 3; i++) {
        // x1 = act(cur) * mask
        act_kernel<<<actGrid, 256>>>(cur, mask, ina + i * CC, inb + i * CC, buf1);
        // conv1 (dilated)
        wnorm_kernel<<<CC, 256>>>(icv + (size_t)i * CC * CC * 3, icg + i * CC, wbuf);
        if (i == 0)
            conv_kernel<1, false, false><<<convGrid, 256>>>(buf1, wbuf, icb + i * CC, nullptr, nullptr, buf2);
        else if (i == 1)
            conv_kernel<3, false, false><<<convGrid, 256>>>(buf1, wbuf, icb + i * CC, nullptr, nullptr, buf2);
        else
            conv_kernel<5, false, false><<<convGrid, 256>>>(buf1, wbuf, icb + i * CC, nullptr, nullptr, buf2);
        // x2 = act(conv1) * mask
        act_kernel<<<actGrid, 256>>>(buf2, mask, outa + i * CC, outb + i * CC, buf1);
        // conv2 (dilation 1) + residual  (+ final mask on last iteration)
        wnorm_kernel<<<CC, 256>>>(ocv + (size_t)i * CC * CC * 3, ocg + i * CC, wbuf);
        if (i == 2)
            conv_kernel<1, true, true><<<convGrid, 256>>>(buf1, wbuf, ocb + i * CC, cur, mask, out);
        else
            conv_kernel<1, true, false><<<convGrid, 256>>>(buf1, wbuf, ocb + i * CC, cur, nullptr, xbuf);
        cur = xbuf;
    }
    (void)in_sizes; (void)n_in; (void)out_size;
}

// round 6
// speedup vs baseline: 2.6281x; 2.6249x over previous
#include <cuda_runtime.h>
#include <cuda_bf16.h>
#include <math.h>
#include <stdint.h>

#define BB 16
#define CC 512
#define TT 4096
#define FK 12
#define ACT_TILE 1024

#define CM 128
#define CN 128
#define CK 32
#define ASTR 40                       // A smem row stride (bf16 elems): 80B, conflict-free
#define XSTR 136                      // X smem row stride: 272B, conflict-free
#define A_E (CM*ASTR)                 // 5120 elems per variant
#define X_E (CK*XSTR)                 // 4352 elems per variant
#define STAGE_E (2*A_E + 2*X_E)       // 18944 elems
#define SMEM_BYTES (2*STAGE_E*2)      // 75776 bytes

// ---------------- device scratch ----------------
__device__ float g_filt[FK];
__device__ __align__(16) __nv_bfloat16 g_whi[3 * CC * CC];                 // [tap][o][c]
__device__ __align__(16) __nv_bfloat16 g_wlo[3 * CC * CC];
__device__ __align__(16) __nv_bfloat16 g_xshhi[(size_t)BB * 3 * CC * TT]; // [b][kt][c][t] pre-shifted
__device__ __align__(16) __nv_bfloat16 g_xshlo[(size_t)BB * 3 * CC * TT];
__device__ __align__(16) float g_buf2[(size_t)BB * CC * TT];
__device__ __align__(16) float g_x[(size_t)BB * CC * TT];

// ---------------- PTX helpers (base ISA only: sm_80/90 features) ----------------
__device__ __forceinline__ uint32_t smem_u32(const void* p) {
    uint32_t a;
    asm("{ .reg .u64 t; cvta.to.shared.u64 t, %1; cvt.u32.u64 %0, t; }" : "=r"(a) : "l"(p));
    return a;
}
__device__ __forceinline__ void cp16(uint32_t d, const void* s) {
    asm volatile("cp.async.cg.shared.global [%0], [%1], 16;" :: "r"(d), "l"(s));
}
__device__ __forceinline__ void ldmA(uint32_t* r, uint32_t addr) {
    asm volatile("ldmatrix.sync.aligned.m8n8.x4.shared.b16 {%0,%1,%2,%3}, [%4];"
        : "=r"(r[0]), "=r"(r[1]), "=r"(r[2]), "=r"(r[3]) : "r"(addr));
}
__device__ __forceinline__ void ldmBT(uint32_t* r, uint32_t addr) {
    asm volatile("ldmatrix.sync.aligned.m8n8.x4.trans.shared.b16 {%0,%1,%2,%3}, [%4];"
        : "=r"(r[0]), "=r"(r[1]), "=r"(r[2]), "=r"(r[3]) : "r"(addr));
}
__device__ __forceinline__ void mma16816(float* d, const uint32_t* a, const uint32_t* b) {
    asm volatile(
        "mma.sync.aligned.m16n8k16.row.col.f32.bf16.bf16.f32 "
        "{%0,%1,%2,%3}, {%4,%5,%6,%7}, {%8,%9}, {%0,%1,%2,%3};"
        : "+f"(d[0]), "+f"(d[1]), "+f"(d[2]), "+f"(d[3])
        : "r"(a[0]), "r"(a[1]), "r"(a[2]), "r"(a[3]), "r"(b[0]), "r"(b[1]));
}

// ---------------- filter init ----------------
__device__ double bessel_i0(double x) {
    double sum = 1.0, term = 1.0;
    for (int k = 1; k < 64; k++) {
        double t = x / (2.0 * k);
        term *= t * t;
        sum += term;
        if (term < 1e-18 * sum) break;
    }
    return sum;
}
__global__ void init_filter_kernel() {
    if (threadIdx.x == 0 && blockIdx.x == 0) {
        const double cutoff = 0.25, half_width = 0.3;
        double delta_f = 4.0 * half_width;
        double A = 2.285 * (FK / 2 - 1) * M_PI * delta_f + 7.95;
        double beta;
        if (A > 50.0)       beta = 0.1102 * (A - 8.7);
        else if (A >= 21.0) beta = 0.5842 * pow(A - 21.0, 0.4) + 0.07886 * (A - 21.0);
        else                beta = 0.0;
        double i0b = bessel_i0(beta);
        double f[FK], s = 0.0;
        for (int n = 0; n < FK; n++) {
            double r = 2.0 * n / (FK - 1.0) - 1.0;
            double w = bessel_i0(beta * sqrt(fmax(0.0, 1.0 - r * r))) / i0b;
            double tm = n - 5.5;
            double xx = 2.0 * cutoff * tm;
            double snc = (fabs(xx) < 1e-12) ? 1.0 : sin(M_PI * xx) / (M_PI * xx);
            f[n] = 2.0 * cutoff * w * snc;
            s += f[n];
        }
        for (int n = 0; n < FK; n++) g_filt[n] = (float)(f[n] / s);
    }
}

// ---------------- fused aliasing activation -> 3 tap-shifted bf16 hi/lo copies ----------------
// xsh[b][kt][c][t] = act(x)[b][c][t + (kt-1)*D], zero outside [0,TT)
template<int D>
__global__ __launch_bounds__(256) void act_kernel(
    const float* __restrict__ x, const float* __restrict__ mask,
    const float* __restrict__ alpha, const float* __restrict__ beta,
    __nv_bfloat16* __restrict__ oh, __nv_bfloat16* __restrict__ ol)
{
    __shared__ float sf[FK];
    __shared__ float sx[ACT_TILE + 12];
    __shared__ float ss[2 * ACT_TILE + 12];

    const int t0 = blockIdx.x * ACT_TILE;
    const int c  = blockIdx.y;
    const int b  = blockIdx.z;
    const int tid = threadIdx.x;
    const float* xr = x + ((size_t)(b * CC + c)) * TT;

    if (tid < FK) sf[tid] = g_filt[tid];
    for (int i = tid; i < ACT_TILE + 12; i += 256) {
        int g = min(max(t0 - 6 + i, 0), TT - 1);
        sx[i] = xr[g];
    }
    __syncthreads();

    const float a    = expf(alpha[c]);
    const float invb = 1.0f / (expf(beta[c]) + 1e-5f);

    for (int si = tid; si < 2 * ACT_TILE + 12; si += 256) {
        const int odd = si & 1;
        const int base = (si + odd) >> 1;
        float u = 0.f;
        #pragma unroll
        for (int j = 0; j < 6; j++) u = fmaf(sf[2 * j + odd], sx[base + j], u);
        u *= 2.0f;
        float sn = __sinf(u * a);
        ss[si] = fmaf(invb, sn * sn, u);
    }
    __syncthreads();

    const float* mrow = mask + (size_t)b * TT;
    const __nv_bfloat16 zb = __float2bfloat16(0.f);
    #pragma unroll
    for (int jj = 0; jj < 4; jj++) {
        const int t = t0 + tid + 256 * jj;
        float z = 0.f;
        #pragma unroll
        for (int k = 0; k < FK; k++) {
            int m = min(max(2 * t + k - 5, 0), 2 * TT - 1);
            z = fmaf(sf[k], ss[m - (2 * t0 - 6)], z);
        }
        float v = z * mrow[t];
        __nv_bfloat16 hi = __float2bfloat16(v);
        __nv_bfloat16 lo = __float2bfloat16(v - __bfloat162float(hi));
        #pragma unroll
        for (int kt = 0; kt < 3; kt++) {
            const int td = t - (kt - 1) * D;
            if (td >= 0 && td < TT) {
                const size_t o = ((size_t)(b * 3 + kt) * CC + c) * TT + td;
                oh[o] = hi;
                ol[o] = lo;
            }
        }
        if (t < D) {             // kt=0 dests [0,D) come from t<0 -> zero
            const size_t o = ((size_t)(b * 3 + 0) * CC + c) * TT + t;
            oh[o] = zb; ol[o] = zb;
        }
        if (t >= TT - D) {       // kt=2 dests [TT-D,TT) come from t>=TT -> zero
            const size_t o = ((size_t)(b * 3 + 2) * CC + c) * TT + t;
            oh[o] = zb; ol[o] = zb;
        }
    }
}

// ---------------- weight norm + bf16 split -> [tap][o][c] ----------------
__global__ __launch_bounds__(256) void wnorm_split_kernel(
    const float* __restrict__ v, const float* __restrict__ g,
    __nv_bfloat16* __restrict__ wh, __nv_bfloat16* __restrict__ wl)
{
    const int o = blockIdx.x;
    const float* vo = v + (size_t)o * (CC * 3);
    __shared__ float red[256];
    float s = 0.f;
    for (int i = threadIdx.x; i < CC * 3; i += 256) { float t = vo[i]; s = fmaf(t, t, s); }
    red[threadIdx.x] = s;
    __syncthreads();
    for (int st = 128; st > 0; st >>= 1) {
        if (threadIdx.x < st) red[threadIdx.x] += red[threadIdx.x + st];
        __syncthreads();
    }
    const float scale = g[o] / sqrtf(red[0]);
    for (int i = threadIdx.x; i < CC * 3; i += 256) {
        int c = i / 3, k = i - 3 * c;
        float w = vo[i] * scale;
        __nv_bfloat16 hi = __float2bfloat16(w);
        size_t dst = ((size_t)k * CC + o) * CC + c;
        wh[dst] = hi;
        wl[dst] = __float2bfloat16(w - __bfloat162float(hi));
    }
}

// ---------------- mma.sync conv GEMM: Y[o,t] = sum_{kt,c} W[kt][o][c] * Xsh[kt][c][t] ----------------
template<bool HAS_RES, bool FUSE_MASK>
__global__ __launch_bounds__(256, 1) void conv_mma_kernel(
    const __nv_bfloat16* __restrict__ wh, const __nv_bfloat16* __restrict__ wl,
    const __nv_bfloat16* __restrict__ xh, const __nv_bfloat16* __restrict__ xl,
    const float* __restrict__ bias, const float* __restrict__ res,
    const float* __restrict__ mask, float* __restrict__ out)
{
    extern __shared__ __nv_bfloat16 smem[];
    const uint32_t sb = smem_u32(smem);
    const int tid = threadIdx.x;
    const int lane = tid & 31;
    const int wid = tid >> 5;
    const int t0 = blockIdx.x * CN;
    const int o0 = blockIdx.y * CM;
    const int b  = blockIdx.z;

    const uint32_t AhO = 0;
    const uint32_t AlO = 2 * A_E;
    const uint32_t XhO = 4 * A_E;
    const uint32_t XlO = 4 * A_E + 2 * X_E;
    const uint32_t STB = 2 * STAGE_E;

    auto load_stage = [&](int ch, int s) {
        const uint32_t st = sb + (uint32_t)s * STB;
        const int kt = ch >> 4;
        const int c0 = (ch & 15) * CK;
        #pragma unroll
        for (int r = 0; r < 2; r++) {
            const int idx = tid + 256 * r;
            const int o_l = idx >> 2, cp = idx & 3;
            const size_t so = ((size_t)(kt * CC + o0 + o_l)) * CC + c0 + cp * 8;
            const uint32_t dof = (uint32_t)(o_l * ASTR + cp * 8) * 2;
            cp16(st + AhO + dof, wh + so);
            cp16(st + AlO + dof, wl + so);
        }
        #pragma unroll
        for (int r = 0; r < 2; r++) {
            const int idx = tid + 256 * r;
            const int c_l = idx >> 4, tp = idx & 15;
            const size_t so = ((size_t)(b * 3 + kt) * CC + c0 + c_l) * TT + t0 + tp * 8;
            const uint32_t dof = (uint32_t)(c_l * XSTR + tp * 8) * 2;
            cp16(st + XhO + dof, xh + so);
            cp16(st + XlO + dof, xl + so);
        }
        asm volatile("cp.async.commit_group;");
    };

    float acc[4][4][4];
    #pragma unroll
    for (int i = 0; i < 4; i++)
        #pragma unroll
        for (int j = 0; j < 4; j++)
            #pragma unroll
            for (int q = 0; q < 4; q++) acc[i][j][q] = 0.f;

    const int wm = (wid >> 2) * 64;
    const int wn = (wid & 3) * 32;

    load_stage(0, 0);
    #pragma unroll 1
    for (int ch = 0; ch < 48; ch++) {
        const int s = ch & 1;
        if (ch + 1 < 48) {
            load_stage(ch + 1, s ^ 1);
            asm volatile("cp.async.wait_group 1;");
        } else {
            asm volatile("cp.async.wait_group 0;");
        }
        __syncthreads();

        const uint32_t st = sb + (uint32_t)s * STB;
        #pragma unroll
        for (int ks = 0; ks < 2; ks++) {
            const int k0 = ks * 16;
            uint32_t ah[4][4], al[4][4], bh[4][2], bl[4][2];
            #pragma unroll
            for (int i = 0; i < 4; i++) {
                const uint32_t ro = (uint32_t)((wm + 16 * i + (lane & 15)) * ASTR
                                               + k0 + (lane >> 4) * 8) * 2;
                ldmA(ah[i], st + AhO + ro);
                ldmA(al[i], st + AlO + ro);
            }
            #pragma unroll
            for (int jj = 0; jj < 2; jj++) {
                const uint32_t ro = (uint32_t)((k0 + (lane & 15)) * XSTR
                                               + wn + 16 * jj + (lane >> 4) * 8) * 2;
                uint32_t rb[4];
                ldmBT(rb, st + XhO + ro);
                bh[2 * jj][0] = rb[0]; bh[2 * jj][1] = rb[1];
                bh[2 * jj + 1][0] = rb[2]; bh[2 * jj + 1][1] = rb[3];
                ldmBT(rb, st + XlO + ro);
                bl[2 * jj][0] = rb[0]; bl[2 * jj][1] = rb[1];
                bl[2 * jj + 1][0] = rb[2]; bl[2 * jj + 1][1] = rb[3];
            }
            #pragma unroll
            for (int i = 0; i < 4; i++)
                #pragma unroll
                for (int j = 0; j < 4; j++) {
                    mma16816(acc[i][j], ah[i], bh[j]);
                    mma16816(acc[i][j], ah[i], bl[j]);
                    mma16816(acc[i][j], al[i], bh[j]);
                }
        }
        __syncthreads();
    }

    // ---- epilogue ----
    const int g = lane >> 2, tg = lane & 3;
    #pragma unroll
    for (int i = 0; i < 4; i++) {
        const int r0 = o0 + wm + 16 * i + g;
        const int r1 = r0 + 8;
        const float b0v = bias[r0], b1v = bias[r1];
        #pragma unroll
        for (int j = 0; j < 4; j++) {
            const int t = t0 + wn + 8 * j + 2 * tg;
            const size_t i0 = ((size_t)(b * CC) + r0) * TT + t;
            const size_t i1 = ((size_t)(b * CC) + r1) * TT + t;
            float v0 = acc[i][j][0] + b0v, v1 = acc[i][j][1] + b0v;
            float v2 = acc[i][j][2] + b1v, v3 = acc[i][j][3] + b1v;
            if (HAS_RES) {
                float2 ra = *(const float2*)(res + i0);
                float2 rb2 = *(const float2*)(res + i1);
                v0 += ra.x; v1 += ra.y; v2 += rb2.x; v3 += rb2.y;
            }
            if (FUSE_MASK) {
                float2 m = *(const float2*)(mask + (size_t)b * TT + t);
                v0 *= m.x; v1 *= m.y; v2 *= m.x; v3 *= m.y;
            }
            *(float2*)(out + i0) = make_float2(v0, v1);
            *(float2*)(out + i1) = make_float2(v2, v3);
        }
    }
}

// ---------------- host ----------------
extern "C" void kernel_launch(void* const* d_in, const int* in_sizes, int n_in,
                              void* d_out, int out_size)
{
    const float* x    = (const float*)d_in[0];
    const float* mask = (const float*)d_in[1];
    const float* ina  = (const float*)d_in[2];
    const float* inb  = (const float*)d_in[3];
    const float* outa = (const float*)d_in[4];
    const float* outb = (const float*)d_in[5];
    const float* icv  = (const float*)d_in[6];
    const float* icg  = (const float*)d_in[7];
    const float* icb  = (const float*)d_in[8];
    const float* ocv  = (const float*)d_in[9];
    const float* ocg  = (const float*)d_in[10];
    const float* ocb  = (const float*)d_in[11];
    float* out = (float*)d_out;

    float *buf2, *xbuf;
    __nv_bfloat16 *xhi, *xlo, *whi, *wlo;
    cudaGetSymbolAddress((void**)&buf2, g_buf2);
    cudaGetSymbolAddress((void**)&xbuf, g_x);
    cudaGetSymbolAddress((void**)&xhi, g_xshhi);
    cudaGetSymbolAddress((void**)&xlo, g_xshlo);
    cudaGetSymbolAddress((void**)&whi, g_whi);
    cudaGetSymbolAddress((void**)&wlo, g_wlo);

    cudaFuncSetAttribute(conv_mma_kernel<false, false>, cudaFuncAttributeMaxDynamicSharedMemorySize, SMEM_BYTES);
    cudaFuncSetAttribute(conv_mma_kernel<true,  false>, cudaFuncAttributeMaxDynamicSharedMemorySize, SMEM_BYTES);
    cudaFuncSetAttribute(conv_mma_kernel<true,  true >, cudaFuncAttributeMaxDynamicSharedMemorySize, SMEM_BYTES);

    init_filter_kernel<<<1, 32>>>();

    const dim3 actGrid(TT / ACT_TILE, CC, BB);
    const dim3 convGrid(TT / CN, CC / CM, BB);

    const float* cur = x;
    for (int i = 0; i < 3; i++) {
        // act1: writes tap-shifted copies with this iteration's dilation
        if (i == 0)      act_kernel<1><<<actGrid, 256>>>(cur, mask, ina + i * CC, inb + i * CC, xhi, xlo);
        else if (i == 1) act_kernel<3><<<actGrid, 256>>>(cur, mask, ina + i * CC, inb + i * CC, xhi, xlo);
        else             act_kernel<5><<<actGrid, 256>>>(cur, mask, ina + i * CC, inb + i * CC, xhi, xlo);
        wnorm_split_kernel<<<CC, 256>>>(icv + (size_t)i * CC * CC * 3, icg + i * CC, whi, wlo);
        conv_mma_kernel<false, false><<<convGrid, 256, SMEM_BYTES>>>(
            whi, wlo, xhi, xlo, icb + i * CC, nullptr, nullptr, buf2);

        // act2: dilation 1
        act_kernel<1><<<actGrid, 256>>>(buf2, mask, outa + i * CC, outb + i * CC, xhi, xlo);
        wnorm_split_kernel<<<CC, 256>>>(ocv + (size_t)i * CC * CC * 3, ocg + i * CC, whi, wlo);
        if (i == 2)
            conv_mma_kernel<true, true><<<convGrid, 256, SMEM_BYTES>>>(
                whi, wlo, xhi, xlo, ocb + i * CC, cur, mask, out);
        else
            conv_mma_kernel<true, false><<<convGrid, 256, SMEM_BYTES>>>(
                whi, wlo, xhi, xlo, ocb + i * CC, cur, nullptr, xbuf);
        cur = xbuf;
    }
    (void)in_sizes; (void)n_in; (void)out_size;
}

// round 7
// speedup vs baseline: 2.6296x; 1.0005x over previous
#include <cuda_runtime.h>
#include <cuda_bf16.h>
#include <math.h>
#include <stdint.h>

#define BB 16
#define CC 512
#define TT 4096
#define FK 12
#define ACT_TILE 1024

#define CM 128
#define CN 128
#define CK 32
#define ASTR 40                       // A smem row stride (bf16 elems): 80B, conflict-free
#define XSTR 136                      // X smem row stride: 272B, conflict-free
#define A_E (CM*ASTR)                 // 5120 elems per variant
#define X_E (CK*XSTR)                 // 4352 elems per variant
#define STAGE_E (2*A_E + 2*X_E)       // 18944 elems
#define SMEM_BYTES (2*STAGE_E*2)      // 75776 bytes

// ---------------- device scratch ----------------
__device__ float g_filt[FK];
__device__ __align__(16) __nv_bfloat16 g_whi[3 * CC * CC];                 // [tap][o][c]
__device__ __align__(16) __nv_bfloat16 g_wlo[3 * CC * CC];
__device__ __align__(16) __nv_bfloat16 g_xshhi[(size_t)BB * 3 * CC * TT]; // [b][kt][c][t] pre-shifted
__device__ __align__(16) __nv_bfloat16 g_xshlo[(size_t)BB * 3 * CC * TT];
__device__ __align__(16) float g_buf2[(size_t)BB * CC * TT];
__device__ __align__(16) float g_x[(size_t)BB * CC * TT];

// ---------------- PTX helpers (base ISA only: sm_80/90 features) ----------------
__device__ __forceinline__ uint32_t smem_u32(const void* p) {
    uint32_t a;
    asm("{ .reg .u64 t; cvta.to.shared.u64 t, %1; cvt.u32.u64 %0, t; }" : "=r"(a) : "l"(p));
    return a;
}
__device__ __forceinline__ void cp16(uint32_t d, const void* s) {
    asm volatile("cp.async.cg.shared.global [%0], [%1], 16;" :: "r"(d), "l"(s));
}
__device__ __forceinline__ void ldmA(uint32_t* r, uint32_t addr) {
    asm volatile("ldmatrix.sync.aligned.m8n8.x4.shared.b16 {%0,%1,%2,%3}, [%4];"
        : "=r"(r[0]), "=r"(r[1]), "=r"(r[2]), "=r"(r[3]) : "r"(addr));
}
__device__ __forceinline__ void ldmBT(uint32_t* r, uint32_t addr) {
    asm volatile("ldmatrix.sync.aligned.m8n8.x4.trans.shared.b16 {%0,%1,%2,%3}, [%4];"
        : "=r"(r[0]), "=r"(r[1]), "=r"(r[2]), "=r"(r[3]) : "r"(addr));
}
__device__ __forceinline__ void mma16816(float* d, const uint32_t* a, const uint32_t* b) {
    asm volatile(
        "mma.sync.aligned.m16n8k16.row.col.f32.bf16.bf16.f32 "
        "{%0,%1,%2,%3}, {%4,%5,%6,%7}, {%8,%9}, {%0,%1,%2,%3};"
        : "+f"(d[0]), "+f"(d[1]), "+f"(d[2]), "+f"(d[3])
        : "r"(a[0]), "r"(a[1]), "r"(a[2]), "r"(a[3]), "r"(b[0]), "r"(b[1]));
}

// ---------------- filter init ----------------
__device__ double bessel_i0(double x) {
    double sum = 1.0, term = 1.0;
    for (int k = 1; k < 64; k++) {
        double t = x / (2.0 * k);
        term *= t * t;
        sum += term;
        if (term < 1e-18 * sum) break;
    }
    return sum;
}
__global__ void init_filter_kernel() {
    if (threadIdx.x == 0 && blockIdx.x == 0) {
        const double cutoff = 0.25, half_width = 0.3;
        double delta_f = 4.0 * half_width;
        double A = 2.285 * (FK / 2 - 1) * M_PI * delta_f + 7.95;
        double beta;
        if (A > 50.0)       beta = 0.1102 * (A - 8.7);
        else if (A >= 21.0) beta = 0.5842 * pow(A - 21.0, 0.4) + 0.07886 * (A - 21.0);
        else                beta = 0.0;
        double i0b = bessel_i0(beta);
        double f[FK], s = 0.0;
        for (int n = 0; n < FK; n++) {
            double r = 2.0 * n / (FK - 1.0) - 1.0;
            double w = bessel_i0(beta * sqrt(fmax(0.0, 1.0 - r * r))) / i0b;
            double tm = n - 5.5;
            double xx = 2.0 * cutoff * tm;
            double snc = (fabs(xx) < 1e-12) ? 1.0 : sin(M_PI * xx) / (M_PI * xx);
            f[n] = 2.0 * cutoff * w * snc;
            s += f[n];
        }
        for (int n = 0; n < FK; n++) g_filt[n] = (float)(f[n] / s);
    }
}

// ---------------- fused aliasing activation -> 3 tap-shifted bf16 hi/lo copies ----------------
// xsh[b][kt][c][t] = act(x)[b][c][t + (kt-1)*D], zero outside [0,TT)
template<int D>
__global__ __launch_bounds__(256) void act_kernel(
    const float* __restrict__ x, const float* __restrict__ mask,
    const float* __restrict__ alpha, const float* __restrict__ beta,
    __nv_bfloat16* __restrict__ oh, __nv_bfloat16* __restrict__ ol)
{
    __shared__ float sf[FK];
    __shared__ float sx[ACT_TILE + 12];
    __shared__ float ss[2 * ACT_TILE + 12];

    const int t0 = blockIdx.x * ACT_TILE;
    const int c  = blockIdx.y;
    const int b  = blockIdx.z;
    const int tid = threadIdx.x;
    const float* xr = x + ((size_t)(b * CC + c)) * TT;

    if (tid < FK) sf[tid] = g_filt[tid];
    for (int i = tid; i < ACT_TILE + 12; i += 256) {
        int g = min(max(t0 - 6 + i, 0), TT - 1);
        sx[i] = xr[g];
    }
    __syncthreads();

    const float a    = expf(alpha[c]);
    const float invb = 1.0f / (expf(beta[c]) + 1e-5f);

    for (int si = tid; si < 2 * ACT_TILE + 12; si += 256) {
        const int odd = si & 1;
        const int base = (si + odd) >> 1;
        float u = 0.f;
        #pragma unroll
        for (int j = 0; j < 6; j++) u = fmaf(sf[2 * j + odd], sx[base + j], u);
        u *= 2.0f;
        float sn = __sinf(u * a);
        ss[si] = fmaf(invb, sn * sn, u);
    }
    __syncthreads();

    const float* mrow = mask + (size_t)b * TT;
    const __nv_bfloat16 zb = __float2bfloat16(0.f);
    #pragma unroll
    for (int jj = 0; jj < 4; jj++) {
        const int t = t0 + tid + 256 * jj;
        float z = 0.f;
        #pragma unroll
        for (int k = 0; k < FK; k++) {
            int m = min(max(2 * t + k - 5, 0), 2 * TT - 1);
            z = fmaf(sf[k], ss[m - (2 * t0 - 6)], z);
        }
        float v = z * mrow[t];
        __nv_bfloat16 hi = __float2bfloat16(v);
        __nv_bfloat16 lo = __float2bfloat16(v - __bfloat162float(hi));
        #pragma unroll
        for (int kt = 0; kt < 3; kt++) {
            const int td = t - (kt - 1) * D;
            if (td >= 0 && td < TT) {
                const size_t o = ((size_t)(b * 3 + kt) * CC + c) * TT + td;
                oh[o] = hi;
                ol[o] = lo;
            }
        }
        if (t < D) {             // kt=0 dests [0,D) come from t<0 -> zero
            const size_t o = ((size_t)(b * 3 + 0) * CC + c) * TT + t;
            oh[o] = zb; ol[o] = zb;
        }
        if (t >= TT - D) {       // kt=2 dests [TT-D,TT) come from t>=TT -> zero
            const size_t o = ((size_t)(b * 3 + 2) * CC + c) * TT + t;
            oh[o] = zb; ol[o] = zb;
        }
    }
}

// ---------------- weight norm + bf16 split -> [tap][o][c] ----------------
__global__ __launch_bounds__(256) void wnorm_split_kernel(
    const float* __restrict__ v, const float* __restrict__ g,
    __nv_bfloat16* __restrict__ wh, __nv_bfloat16* __restrict__ wl)
{
    const int o = blockIdx.x;
    const float* vo = v + (size_t)o * (CC * 3);
    __shared__ float red[256];
    float s = 0.f;
    for (int i = threadIdx.x; i < CC * 3; i += 256) { float t = vo[i]; s = fmaf(t, t, s); }
    red[threadIdx.x] = s;
    __syncthreads();
    for (int st = 128; st > 0; st >>= 1) {
        if (threadIdx.x < st) red[threadIdx.x] += red[threadIdx.x + st];
        __syncthreads();
    }
    const float scale = g[o] / sqrtf(red[0]);
    for (int i = threadIdx.x; i < CC * 3; i += 256) {
        int c = i / 3, k = i - 3 * c;
        float w = vo[i] * scale;
        __nv_bfloat16 hi = __float2bfloat16(w);
        size_t dst = ((size_t)k * CC + o) * CC + c;
        wh[dst] = hi;
        wl[dst] = __float2bfloat16(w - __bfloat162float(hi));
    }
}

// ---------------- mma.sync conv GEMM: Y[o,t] = sum_{kt,c} W[kt][o][c] * Xsh[kt][c][t] ----------------
template<bool HAS_RES, bool FUSE_MASK>
__global__ __launch_bounds__(256, 1) void conv_mma_kernel(
    const __nv_bfloat16* __restrict__ wh, const __nv_bfloat16* __restrict__ wl,
    const __nv_bfloat16* __restrict__ xh, const __nv_bfloat16* __restrict__ xl,
    const float* __restrict__ bias, const float* __restrict__ res,
    const float* __restrict__ mask, float* __restrict__ out)
{
    extern __shared__ __nv_bfloat16 smem[];
    const uint32_t sb = smem_u32(smem);
    const int tid = threadIdx.x;
    const int lane = tid & 31;
    const int wid = tid >> 5;
    const int t0 = blockIdx.x * CN;
    const int o0 = blockIdx.y * CM;
    const int b  = blockIdx.z;

    const uint32_t AhO = 0;
    const uint32_t AlO = 2 * A_E;
    const uint32_t XhO = 4 * A_E;
    const uint32_t XlO = 4 * A_E + 2 * X_E;
    const uint32_t STB = 2 * STAGE_E;

    auto load_stage = [&](int ch, int s) {
        const uint32_t st = sb + (uint32_t)s * STB;
        const int kt = ch >> 4;
        const int c0 = (ch & 15) * CK;
        #pragma unroll
        for (int r = 0; r < 2; r++) {
            const int idx = tid + 256 * r;
            const int o_l = idx >> 2, cp = idx & 3;
            const size_t so = ((size_t)(kt * CC + o0 + o_l)) * CC + c0 + cp * 8;
            const uint32_t dof = (uint32_t)(o_l * ASTR + cp * 8) * 2;
            cp16(st + AhO + dof, wh + so);
            cp16(st + AlO + dof, wl + so);
        }
        #pragma unroll
        for (int r = 0; r < 2; r++) {
            const int idx = tid + 256 * r;
            const int c_l = idx >> 4, tp = idx & 15;
            const size_t so = ((size_t)(b * 3 + kt) * CC + c0 + c_l) * TT + t0 + tp * 8;
            const uint32_t dof = (uint32_t)(c_l * XSTR + tp * 8) * 2;
            cp16(st + XhO + dof, xh + so);
            cp16(st + XlO + dof, xl + so);
        }
        asm volatile("cp.async.commit_group;");
    };

    float acc[4][4][4];
    #pragma unroll
    for (int i = 0; i < 4; i++)
        #pragma unroll
        for (int j = 0; j < 4; j++)
            #pragma unroll
            for (int q = 0; q < 4; q++) acc[i][j][q] = 0.f;

    const int wm = (wid >> 2) * 64;
    const int wn = (wid & 3) * 32;

    load_stage(0, 0);
    #pragma unroll 1
    for (int ch = 0; ch < 48; ch++) {
        const int s = ch & 1;
        if (ch + 1 < 48) {
            load_stage(ch + 1, s ^ 1);
            asm volatile("cp.async.wait_group 1;");
        } else {
            asm volatile("cp.async.wait_group 0;");
        }
        __syncthreads();

        const uint32_t st = sb + (uint32_t)s * STB;
        #pragma unroll
        for (int ks = 0; ks < 2; ks++) {
            const int k0 = ks * 16;
            uint32_t ah[4][4], al[4][4], bh[4][2], bl[4][2];
            #pragma unroll
            for (int i = 0; i < 4; i++) {
                const uint32_t ro = (uint32_t)((wm + 16 * i + (lane & 15)) * ASTR
                                               + k0 + (lane >> 4) * 8) * 2;
                ldmA(ah[i], st + AhO + ro);
                ldmA(al[i], st + AlO + ro);
            }
            #pragma unroll
            for (int jj = 0; jj < 2; jj++) {
                const uint32_t ro = (uint32_t)((k0 + (lane & 15)) * XSTR
                                               + wn + 16 * jj + (lane >> 4) * 8) * 2;
                uint32_t rb[4];
                ldmBT(rb, st + XhO + ro);
                bh[2 * jj][0] = rb[0]; bh[2 * jj][1] = rb[1];
                bh[2 * jj + 1][0] = rb[2]; bh[2 * jj + 1][1] = rb[3];
                ldmBT(rb, st + XlO + ro);
                bl[2 * jj][0] = rb[0]; bl[2 * jj][1] = rb[1];
                bl[2 * jj + 1][0] = rb[2]; bl[2 * jj + 1][1] = rb[3];
            }
            #pragma unroll
            for (int i = 0; i < 4; i++)
                #pragma unroll
                for (int j = 0; j < 4; j++) {
                    mma16816(acc[i][j], ah[i], bh[j]);
                    mma16816(acc[i][j], ah[i], bl[j]);
                    mma16816(acc[i][j], al[i], bh[j]);
                }
        }
        __syncthreads();
    }

    // ---- epilogue ----
    const int g = lane >> 2, tg = lane & 3;
    #pragma unroll
    for (int i = 0; i < 4; i++) {
        const int r0 = o0 + wm + 16 * i + g;
        const int r1 = r0 + 8;
        const float b0v = bias[r0], b1v = bias[r1];
        #pragma unroll
        for (int j = 0; j < 4; j++) {
            const int t = t0 + wn + 8 * j + 2 * tg;
            const size_t i0 = ((size_t)(b * CC) + r0) * TT + t;
            const size_t i1 = ((size_t)(b * CC) + r1) * TT + t;
            float v0 = acc[i][j][0] + b0v, v1 = acc[i][j][1] + b0v;
            float v2 = acc[i][j][2] + b1v, v3 = acc[i][j][3] + b1v;
            if (HAS_RES) {
                float2 ra = *(const float2*)(res + i0);
                float2 rb2 = *(const float2*)(res + i1);
                v0 += ra.x; v1 += ra.y; v2 += rb2.x; v3 += rb2.y;
            }
            if (FUSE_MASK) {
                float2 m = *(const float2*)(mask + (size_t)b * TT + t);
                v0 *= m.x; v1 *= m.y; v2 *= m.x; v3 *= m.y;
            }
            *(float2*)(out + i0) = make_float2(v0, v1);
            *(float2*)(out + i1) = make_float2(v2, v3);
        }
    }
}

// ---------------- host ----------------
extern "C" void kernel_launch(void* const* d_in, const int* in_sizes, int n_in,
                              void* d_out, int out_size)
{
    const float* x    = (const float*)d_in[0];
    const float* mask = (const float*)d_in[1];
    const float* ina  = (const float*)d_in[2];
    const float* inb  = (const float*)d_in[3];
    const float* outa = (const float*)d_in[4];
    const float* outb = (const float*)d_in[5];
    const float* icv  = (const float*)d_in[6];
    const float* icg  = (const float*)d_in[7];
    const float* icb  = (const float*)d_in[8];
    const float* ocv  = (const float*)d_in[9];
    const float* ocg  = (const float*)d_in[10];
    const float* ocb  = (const float*)d_in[11];
    float* out = (float*)d_out;

    float *buf2, *xbuf;
    __nv_bfloat16 *xhi, *xlo, *whi, *wlo;
    cudaGetSymbolAddress((void**)&buf2, g_buf2);
    cudaGetSymbolAddress((void**)&xbuf, g_x);
    cudaGetSymbolAddress((void**)&xhi, g_xshhi);
    cudaGetSymbolAddress((void**)&xlo, g_xshlo);
    cudaGetSymbolAddress((void**)&whi, g_whi);
    cudaGetSymbolAddress((void**)&wlo, g_wlo);

    cudaFuncSetAttribute(conv_mma_kernel<false, false>, cudaFuncAttributeMaxDynamicSharedMemorySize, SMEM_BYTES);
    cudaFuncSetAttribute(conv_mma_kernel<true,  false>, cudaFuncAttributeMaxDynamicSharedMemorySize, SMEM_BYTES);
    cudaFuncSetAttribute(conv_mma_kernel<true,  true >, cudaFuncAttributeMaxDynamicSharedMemorySize, SMEM_BYTES);

    init_filter_kernel<<<1, 32>>>();

    const dim3 actGrid(TT / ACT_TILE, CC, BB);
    const dim3 convGrid(TT / CN, CC / CM, BB);

    const float* cur = x;
    for (int i = 0; i < 3; i++) {
        // act1: writes tap-shifted copies with this iteration's dilation
        if (i == 0)      act_kernel<1><<<actGrid, 256>>>(cur, mask, ina + i * CC, inb + i * CC, xhi, xlo);
        else if (i == 1) act_kernel<3><<<actGrid, 256>>>(cur, mask, ina + i * CC, inb + i * CC, xhi, xlo);
        else             act_kernel<5><<<actGrid, 256>>>(cur, mask, ina + i * CC, inb + i * CC, xhi, xlo);
        wnorm_split_kernel<<<CC, 256>>>(icv + (size_t)i * CC * CC * 3, icg + i * CC, whi, wlo);
        conv_mma_kernel<false, false><<<convGrid, 256, SMEM_BYTES>>>(
            whi, wlo, xhi, xlo, icb + i * CC, nullptr, nullptr, buf2);

        // act2: dilation 1
        act_kernel<1><<<actGrid, 256>>>(buf2, mask, outa + i * CC, outb + i * CC, xhi, xlo);
        wnorm_split_kernel<<<CC, 256>>>(ocv + (size_t)i * CC * CC * 3, ocg + i * CC, whi, wlo);
        if (i == 2)
            conv_mma_kernel<true, true><<<convGrid, 256, SMEM_BYTES>>>(
                whi, wlo, xhi, xlo, ocb + i * CC, cur, mask, out);
        else
            conv_mma_kernel<true, false><<<convGrid, 256, SMEM_BYTES>>>(
                whi, wlo, xhi, xlo, ocb + i * CC, cur, nullptr, xbuf);
        cur = xbuf;
    }
    (void)in_sizes; (void)n_in; (void)out_size;
}